// round 16
// baseline (speedup 1.0000x reference)
#include <cuda_runtime.h>
#include <cuda_fp16.h>
#include <cstdint>
#include <cstddef>

// Problem constants
#define BB 4
#define TT 2048
#define CC 1024
#define HH 16
#define DD 64
#define C3 (3 * CC)
#define GK 1024   // K of both dense GEMMs

// Scratch (allocation-free rule: __device__ globals)
__device__ __half g_kqvh[(size_t)BB * TT * C3]; // [B,T,3C] (k|q|v) fp16
__device__ __half g_yh[(size_t)BB * TT * CC];   // [B,T,C] fp16
__device__ __half g_xh[(size_t)BB * TT * CC];   // x fp16
__device__ __half g_wkh[(size_t)CC * C3];       // W_kqv fp16, natural [K,N]
__device__ __half g_wph[(size_t)CC * CC];       // W_proj fp16, natural [K,N]

// ---------------------------------------------------------------------------
// Helpers
// ---------------------------------------------------------------------------
__device__ __forceinline__ uint32_t packh2(float lo, float hi) {
    uint32_t r;
    asm("cvt.rn.f16x2.f32 %0, %1, %2;" : "=r"(r) : "f"(hi), "f"(lo));
    return r;
}
__device__ __forceinline__ uint32_t hex2(uint32_t a) {
    uint32_t r;
    asm("ex2.approx.f16x2 %0, %1;" : "=r"(r) : "r"(a));
    return r;
}
__device__ __forceinline__ uint32_t hadd2(uint32_t a, uint32_t b) {
    uint32_t r;
    asm("add.rn.f16x2 %0, %1, %2;" : "=r"(r) : "r"(a), "r"(b));
    return r;
}
__device__ __forceinline__ float2 h22f2(uint32_t u) {
    __half2 h = *reinterpret_cast<__half2*>(&u);
    return __half22float2(h);
}
__device__ __forceinline__ void mma_f16(float* d, const uint32_t* a, const uint32_t* b) {
    asm volatile(
        "mma.sync.aligned.m16n8k16.row.col.f32.f16.f16.f32 "
        "{%0,%1,%2,%3}, {%4,%5,%6,%7}, {%8,%9}, {%0,%1,%2,%3};"
        : "+f"(d[0]), "+f"(d[1]), "+f"(d[2]), "+f"(d[3])
        : "r"(a[0]), "r"(a[1]), "r"(a[2]), "r"(a[3]), "r"(b[0]), "r"(b[1]));
}
__device__ __forceinline__ void ldsm4(uint32_t* r, uint32_t addr) {
    asm volatile("ldmatrix.sync.aligned.m8n8.x4.shared.b16 {%0,%1,%2,%3}, [%4];"
                 : "=r"(r[0]), "=r"(r[1]), "=r"(r[2]), "=r"(r[3]) : "r"(addr));
}
__device__ __forceinline__ void ldsm4t(uint32_t* r, uint32_t addr) {
    asm volatile("ldmatrix.sync.aligned.m8n8.x4.trans.shared.b16 {%0,%1,%2,%3}, [%4];"
                 : "=r"(r[0]), "=r"(r[1]), "=r"(r[2]), "=r"(r[3]) : "r"(addr));
}
__device__ __forceinline__ uint32_t smem_u32(const void* p) {
    return (uint32_t)__cvta_generic_to_shared(p);
}
__device__ __forceinline__ void cp16(uint32_t s, const void* g) {
    asm volatile("cp.async.cg.shared.global [%0], [%1], 16;" :: "r"(s), "l"(g));
}
__device__ __forceinline__ void cp_commit() {
    asm volatile("cp.async.commit_group;" ::: "memory");
}
template <int n>
__device__ __forceinline__ void cp_wait() {
    asm volatile("cp.async.wait_group %0;" :: "n"(n) : "memory");
}

#define SWZ128(o) ((o) ^ (((o) >> 3) & 0x70))

// ---------------------------------------------------------------------------
// Prep: fp32 -> fp16 copy (1024 elems per block)
// ---------------------------------------------------------------------------
__global__ void half_copy(const float* __restrict__ in, __half* __restrict__ out) {
    const int i = (blockIdx.x * 256 + threadIdx.x) * 4;
    float4 v = *(const float4*)(in + i);
    uint2 o;
    o.x = packh2(v.x, v.y);
    o.y = packh2(v.z, v.w);
    *(uint2*)(out + i) = o;
}

// ---------------------------------------------------------------------------
// FP16 m16n8k16 GEMM with bias: C[M,N] = A[M,1024] @ B[1024,N] + bias[N]
// CTA tile 128x128, BK=64, 256 threads (8 warps, 2Mx4N), warp tile 64x32.
// 3-stage cp.async ring (32KB/stage = 96KB total) + <=128 regs so TWO CTAs
// co-reside per SM: one CTA issues HMMA while the other waits at its barrier.
// A: [128][64] fp16, 128B rows, SW128. B: [64][128] fp16, 256B rows,
// chunk-swizzle c16^(k&7). One __syncthreads per K-tile.
// ---------------------------------------------------------------------------
#define SMA(s) ((s) * 32768)
#define SMB(s) ((s) * 32768 + 16384)
#define GSMEM  98304

__device__ __forceinline__ void gemm_copy_tile(
    uint32_t sb, int s, const __half* __restrict__ A, const __half* __restrict__ B,
    int bm, int bn, int k0, int N, int tid)
{
#pragma unroll
    for (int i = 0; i < 4; i++) {
        const int c = tid + i * 256;      // 0..1023
        const int row = c >> 3;           // 0..127
        const int c8 = c & 7;             // 16B chunk in 128B row
        cp16(sb + SMA(s) + SWZ128((uint32_t)(row * 128 + c8 * 16)),
             A + (size_t)(bm + row) * GK + k0 + c8 * 8);
    }
#pragma unroll
    for (int i = 0; i < 4; i++) {
        const int c = tid + i * 256;      // 0..1023
        const int k = c >> 4;             // 0..63
        const int c16 = c & 15;           // 16B chunk in 256B row
        cp16(sb + SMB(s) + k * 256 + ((uint32_t)(c16 ^ (k & 7)) << 4),
             B + (size_t)(k0 + k) * N + bn + c16 * 8);
    }
}

__global__ void __launch_bounds__(256, 2) gemm_f16_bias(
    const __half* __restrict__ A, const __half* __restrict__ Bm,
    const float* __restrict__ bias, void* __restrict__ Cm, int N, int half_out)
{
    extern __shared__ char smem[];
    const uint32_t sb = smem_u32(smem);
    const int tid  = threadIdx.x;
    const int warp = tid >> 5;
    const int lane = tid & 31;
    const int grp  = lane >> 3;
    const int bm = blockIdx.y * 128;
    const int bn = blockIdx.x * 128;

    const int warpM = (warp >> 2) * 64;   // 0 or 64
    const int warpN = (warp & 3) * 32;    // 0,32,64,96
    const int wN16  = warpN >> 3;         // base 16B chunk (n8 tiles)

    float acc[4][4][4];
#pragma unroll
    for (int i = 0; i < 4; i++)
#pragma unroll
        for (int j = 0; j < 4; j++)
#pragma unroll
            for (int e = 0; e < 4; e++) acc[i][j][e] = 0.0f;

    gemm_copy_tile(sb, 0, A, Bm, bm, bn, 0, N, tid);
    cp_commit();
    gemm_copy_tile(sb, 1, A, Bm, bm, bn, 64, N, tid);
    cp_commit();

    const int NT = GK / 64;  // 16
    for (int t = 0; t < NT; t++) {
        if (t == NT - 1) cp_wait<0>(); else cp_wait<1>();
        __syncthreads();

        // Refill stage (t+2)%3 (its compute finished last iteration)
        if (t + 2 < NT) {
            gemm_copy_tile(sb, (t + 2) % 3, A, Bm, bm, bn, (t + 2) * 64, N, tid);
            cp_commit();
        }

        const int s = t % 3;
        const uint32_t sA = sb + SMA(s);
        const uint32_t sB = sb + SMB(s);
#pragma unroll
        for (int ks = 0; ks < 4; ks++) {
            uint32_t af[4][4];
#pragma unroll
            for (int mt = 0; mt < 4; mt++) {
                const int row = warpM + mt * 16 + (lane & 15);
                ldsm4(af[mt], sA + SWZ128(
                    (uint32_t)(row * 128 + ks * 32 + ((lane >> 4) & 1) * 16)));
            }
#pragma unroll
            for (int p = 0; p < 2; p++) {
                uint32_t bf[4];
                const int k = ks * 16 + (grp & 1) * 8 + (lane & 7);
                const int c16 = wN16 + 2 * p + (grp >> 1);
                ldsm4t(bf, sB + k * 256 + ((uint32_t)(c16 ^ (k & 7)) << 4));
#pragma unroll
                for (int mt = 0; mt < 4; mt++) {
                    mma_f16(acc[mt][2 * p],     af[mt], bf);
                    mma_f16(acc[mt][2 * p + 1], af[mt], bf + 2);
                }
            }
        }
    }

    // Epilogue: C = acc + bias
    const int lr = lane >> 2, c2 = (lane & 3) * 2;
#pragma unroll
    for (int mt = 0; mt < 4; mt++) {
#pragma unroll
        for (int nt = 0; nt < 4; nt++) {
            const int grow = bm + warpM + mt * 16 + lr;
            const int gcol = bn + warpN + nt * 8 + c2;
            const float b0 = bias[gcol];
            const float b1 = bias[gcol + 1];
            const float v00 = acc[mt][nt][0] + b0;
            const float v01 = acc[mt][nt][1] + b1;
            const float v10 = acc[mt][nt][2] + b0;
            const float v11 = acc[mt][nt][3] + b1;
            if (half_out) {
                uint32_t* co = (uint32_t*)Cm;
                co[((size_t)grow * N + gcol) >> 1]       = packh2(v00, v01);
                co[((size_t)(grow + 8) * N + gcol) >> 1] = packh2(v10, v11);
            } else {
                float* cf = (float*)Cm;
                *(float2*)(cf + (size_t)grow * N + gcol)       = make_float2(v00, v01);
                *(float2*)(cf + (size_t)(grow + 8) * N + gcol) = make_float2(v10, v11);
            }
        }
    }
}

// ---------------------------------------------------------------------------
// Flash attention v6 (R14, validated): fp16 m16n8k16 + ldmatrix, BQ=128,
// BK=64, fp16-native softmax, 3-stage K/V ring, one barrier per tile.
// ---------------------------------------------------------------------------
#define AQ 128
#define AK 64
#define ASMEM 65536

__device__ __forceinline__ void attn_fill(
    uint32_t sK, uint32_t sV, const __half* __restrict__ kb,
    const __half* __restrict__ vb, int j0, int tid)
{
#pragma unroll
    for (int i = 0; i < 4; i++) {
        const int cc = tid + (i & 1) * 256;   // 0..511
        const int j = cc >> 3;
        const int c8 = cc & 7;
        const uint32_t off = SWZ128((uint32_t)(j * 128 + c8 * 16));
        if (i < 2) cp16(sK + off, kb + (size_t)(j0 + j) * C3 + c8 * 8);
        else       cp16(sV + off, vb + (size_t)(j0 + j) * C3 + c8 * 8);
    }
}

__global__ void __launch_bounds__(256) attn_kernel(
    const __half* __restrict__ kqvh, const int* __restrict__ padmask,
    __half* __restrict__ y)
{
    extern __shared__ char asmem[];
    const uint32_t sb = smem_u32(asmem);

    const int q0 = blockIdx.x * AQ;
    const int h  = blockIdx.y;
    const int b  = blockIdx.z;
    const int tid = threadIdx.x;
    const int warp = tid >> 5;
    const int lane = tid & 31;
    const int q = lane & 3;
    const int grp = lane >> 3;
    const float c_scale = 0.18033688011112042f;  // 0.125 * log2(e)

    const __half* base  = kqvh + (size_t)b * TT * C3 + (size_t)h * DD;
    const __half* qbase = base + CC;
    const __half* kbase = base;
    const __half* vbase = base + 2 * CC;

    // ---- Prologue: cp.async Q, KV tiles 0 and 1 ----
#pragma unroll
    for (int i = 0; i < 4; i++) {
        const int c = tid + i * 256;
        const int r = c >> 3;
        const int c8 = c & 7;
        cp16(sb + SWZ128((uint32_t)(r * 128 + c8 * 16)),
             qbase + (size_t)(q0 + r) * C3 + c8 * 8);
    }
    cp_commit();
    attn_fill(sb + 16384, sb + 16384 + 8192, kbase, vbase, 0, tid);
    cp_commit();
    attn_fill(sb + 32768, sb + 32768 + 8192, kbase, vbase, AK, tid);
    cp_commit();

    cp_wait<2>();   // Q ready
    __syncthreads();

    uint32_t aq_[4][4];
#pragma unroll
    for (int ks = 0; ks < 4; ks++) {
        const uint32_t addr = sb + SWZ128(
            (uint32_t)((16 * warp + (lane & 15)) * 128 + ks * 32 + ((lane >> 4) & 1) * 16));
        ldsm4(aq_[ks], addr);
    }

    const int r0 = warp * 16 + (lane >> 2);
    const int r1 = r0 + 8;

    float oacc[8][4];
#pragma unroll
    for (int nt = 0; nt < 8; nt++)
#pragma unroll
        for (int e = 0; e < 4; e++) oacc[nt][e] = 0.0f;
    float m0 = -1e20f, m1 = -1e20f, l0 = 0.0f, l1 = 0.0f;

    const int ntiles = (q0 + AQ) / AK;   // >= 2

    for (int t = 0; t < ntiles; t++) {
        const int j0 = t * AK;
        if (t == ntiles - 1) cp_wait<0>(); else cp_wait<1>();
        __syncthreads();

        if (t + 2 < ntiles) {
            const uint32_t st = sb + 16384 + ((t + 2) % 3) * 16384;
            attn_fill(st, st + 8192, kbase, vbase, (t + 2) * AK, tid);
            cp_commit();
        }

        const bool active = (j0 <= q0 + warp * 16 + 15);  // warp-uniform
        if (active) {
            const uint32_t sK = sb + 16384 + (t % 3) * 16384;
            const uint32_t sV = sK + 8192;

            const uint32_t pb0 =
                __ballot_sync(0xffffffffu, padmask[b * TT + j0 + lane] != 0);
            const uint32_t pb1 =
                __ballot_sync(0xffffffffu, padmask[b * TT + j0 + 32 + lane] != 0);

            // ---- S = Q K^T ----
            float sacc[8][4];
#pragma unroll
            for (int nt = 0; nt < 8; nt++)
#pragma unroll
                for (int e = 0; e < 4; e++) sacc[nt][e] = 0.0f;
#pragma unroll
            for (int ks = 0; ks < 4; ks++) {
#pragma unroll
                for (int p = 0; p < 4; p++) {
                    uint32_t kf[4];
                    const int row = (2 * p + (grp >> 1)) * 8 + (lane & 7);
                    const uint32_t addr = sK + SWZ128(
                        (uint32_t)(row * 128 + ks * 32 + (grp & 1) * 16));
                    ldsm4(kf, addr);
                    mma_f16(sacc[2 * p],     aq_[ks], kf);
                    mma_f16(sacc[2 * p + 1], aq_[ks], kf + 2);
                }
            }

            // ---- Mask (raw domain): invalid -> -1e30 ----
            const bool fast =
                (j0 + AK - 1 <= q0 + warp * 16) && (pb0 & pb1) == 0xffffffffu;
            if (!fast) {
#pragma unroll
                for (int nt = 0; nt < 8; nt++) {
                    const int c0 = nt * 8 + 2 * q;
                    const int c1 = c0 + 1;
                    const bool p0v = (((c0 < 32 ? pb0 : pb1) >> (c0 & 31)) & 1u) != 0;
                    const bool p1v = (((c1 < 32 ? pb0 : pb1) >> (c1 & 31)) & 1u) != 0;
                    const int k0g = j0 + c0, k1g = j0 + c1;
                    if (!(p0v && k0g <= q0 + r0)) sacc[nt][0] = -1e30f;
                    if (!(p1v && k1g <= q0 + r0)) sacc[nt][1] = -1e30f;
                    if (!(p0v && k0g <= q0 + r1)) sacc[nt][2] = -1e30f;
                    if (!(p1v && k1g <= q0 + r1)) sacc[nt][3] = -1e30f;
                }
            }

            // ---- Row max on RAW scores ----
            float rm0 = -1e30f, rm1 = -1e30f;
#pragma unroll
            for (int nt = 0; nt < 8; nt++) {
                rm0 = fmaxf(rm0, fmaxf(sacc[nt][0], sacc[nt][1]));
                rm1 = fmaxf(rm1, fmaxf(sacc[nt][2], sacc[nt][3]));
            }
            rm0 = fmaxf(rm0, __shfl_xor_sync(0xffffffffu, rm0, 1));
            rm0 = fmaxf(rm0, __shfl_xor_sync(0xffffffffu, rm0, 2));
            rm1 = fmaxf(rm1, __shfl_xor_sync(0xffffffffu, rm1, 1));
            rm1 = fmaxf(rm1, __shfl_xor_sync(0xffffffffu, rm1, 2));

            const float mn0 = fmaxf(m0, rm0 * c_scale);
            const float mn1 = fmaxf(m1, rm1 * c_scale);
            const float alpha0 = exp2f(m0 - mn0);
            const float alpha1 = exp2f(m1 - mn1);
            m0 = mn0; m1 = mn1;
            const float nm0 = -m0, nm1 = -m1;

            // ---- exp in packed fp16 (outputs ARE PV A-frags) + rescale ----
            uint32_t Pp[8][2];
#pragma unroll
            for (int nt = 0; nt < 8; nt++) {
                const float t00 = fmaf(sacc[nt][0], c_scale, nm0);
                const float t01 = fmaf(sacc[nt][1], c_scale, nm0);
                const float t10 = fmaf(sacc[nt][2], c_scale, nm1);
                const float t11 = fmaf(sacc[nt][3], c_scale, nm1);
                Pp[nt][0] = hex2(packh2(t00, t01));
                Pp[nt][1] = hex2(packh2(t10, t11));
                oacc[nt][0] *= alpha0; oacc[nt][1] *= alpha0;
                oacc[nt][2] *= alpha1; oacc[nt][3] *= alpha1;
            }

            // ---- Row sums: depth-2 HADD2 tree, finish in fp32 ----
            {
                const uint32_t u0 = hadd2(hadd2(Pp[0][0], Pp[1][0]),
                                          hadd2(Pp[2][0], Pp[3][0]));
                const uint32_t u1 = hadd2(hadd2(Pp[4][0], Pp[5][0]),
                                          hadd2(Pp[6][0], Pp[7][0]));
                const uint32_t v0 = hadd2(hadd2(Pp[0][1], Pp[1][1]),
                                          hadd2(Pp[2][1], Pp[3][1]));
                const uint32_t v1 = hadd2(hadd2(Pp[4][1], Pp[5][1]),
                                          hadd2(Pp[6][1], Pp[7][1]));
                const float2 a = h22f2(u0), bb = h22f2(u1);
                const float2 cfv = h22f2(v0), d = h22f2(v1);
                float ps0 = (a.x + a.y) + (bb.x + bb.y);
                float ps1 = (cfv.x + cfv.y) + (d.x + d.y);
                ps0 += __shfl_xor_sync(0xffffffffu, ps0, 1);
                ps0 += __shfl_xor_sync(0xffffffffu, ps0, 2);
                ps1 += __shfl_xor_sync(0xffffffffu, ps1, 1);
                ps1 += __shfl_xor_sync(0xffffffffu, ps1, 2);
                l0 = l0 * alpha0 + ps0;
                l1 = l1 * alpha1 + ps1;
            }

            // ---- O += P V ----
#pragma unroll
            for (int kc = 0; kc < 4; kc++) {
                uint32_t pa[4];
                pa[0] = Pp[2 * kc][0];
                pa[1] = Pp[2 * kc][1];
                pa[2] = Pp[2 * kc + 1][0];
                pa[3] = Pp[2 * kc + 1][1];
#pragma unroll
                for (int p = 0; p < 4; p++) {
                    uint32_t vf[4];
                    const int row = kc * 16 + (grp & 1) * 8 + (lane & 7);
                    const int c16 = 2 * p + (grp >> 1);
                    const uint32_t addr = sV + SWZ128((uint32_t)(row * 128 + c16 * 16));
                    ldsm4t(vf, addr);
                    mma_f16(oacc[2 * p],     pa, vf);
                    mma_f16(oacc[2 * p + 1], pa, vf + 2);
                }
            }
        }
    }

    // ---- Epilogue: normalize + store fp16 y ----
    {
        const float inv0 = 1.0f / l0;
        const float inv1 = 1.0f / l1;
        uint32_t* yw = (uint32_t*)y;
        const size_t o0 = ((size_t)b * TT + q0 + r0) * CC + h * DD;
        const size_t o1 = ((size_t)b * TT + q0 + r1) * CC + h * DD;
#pragma unroll
        for (int nt = 0; nt < 8; nt++) {
            const int c = nt * 8 + 2 * q;
            yw[(o0 + c) >> 1] = packh2(oacc[nt][0] * inv0, oacc[nt][1] * inv0);
            yw[(o1 + c) >> 1] = packh2(oacc[nt][2] * inv1, oacc[nt][3] * inv1);
        }
    }
}

// ---------------------------------------------------------------------------
extern "C" void kernel_launch(void* const* d_in, const int* in_sizes, int n_in,
                              void* d_out, int out_size)
{
    const float* x      = (const float*)d_in[0];
    const float* W_kqv  = (const float*)d_in[1];
    const float* b_kqv  = (const float*)d_in[2];
    const float* W_proj = (const float*)d_in[3];
    const float* b_proj = (const float*)d_in[4];
    const int*   pad    = (const int*)d_in[5];
    float* out = (float*)d_out;

    __half *kqvh_ptr, *yh_ptr, *xh_ptr, *wkh_ptr, *wph_ptr;
    cudaGetSymbolAddress((void**)&kqvh_ptr, g_kqvh);
    cudaGetSymbolAddress((void**)&yh_ptr, g_yh);
    cudaGetSymbolAddress((void**)&xh_ptr, g_xh);
    cudaGetSymbolAddress((void**)&wkh_ptr, g_wkh);
    cudaGetSymbolAddress((void**)&wph_ptr, g_wph);

    const int M = BB * TT;  // 8192

    cudaFuncSetAttribute(gemm_f16_bias,
                         cudaFuncAttributeMaxDynamicSharedMemorySize, GSMEM);
    cudaFuncSetAttribute(attn_kernel,
                         cudaFuncAttributeMaxDynamicSharedMemorySize, ASMEM);

    // 0) Prep: convert x and weights to fp16
    half_copy<<<(M * CC) / 1024, 256>>>(x, xh_ptr);
    half_copy<<<(CC * C3) / 1024, 256>>>(W_kqv, wkh_ptr);
    half_copy<<<(CC * CC) / 1024, 256>>>(W_proj, wph_ptr);

    // 1) kqv = x @ W_kqv + b_kqv  [8192, 3072], fp16 output
    {
        dim3 grid(C3 / 128, M / 128);
        gemm_f16_bias<<<grid, 256, GSMEM>>>(xh_ptr, wkh_ptr, b_kqv, kqvh_ptr, C3, 1);
    }
    // 2) flash attention (fp16 MMA, fp16 softmax) -> y fp16  [8192, 1024]
    {
        dim3 grid(TT / AQ, HH, BB);
        attn_kernel<<<grid, 256, ASMEM>>>(kqvh_ptr, pad, yh_ptr);
    }
    // 3) out = y @ W_proj + b_proj  [8192, 1024], fp32 output
    {
        dim3 grid(CC / 128, M / 128);
        gemm_f16_bias<<<grid, 256, GSMEM>>>(yh_ptr, wph_ptr, b_proj, out, CC, 0);
    }
}